// round 2
// baseline (speedup 1.0000x reference)
#include <cuda_runtime.h>
#include <cuda_bf16.h>
#include <cstdint>

#define DI __device__ __forceinline__

// ---------------- problem dims ----------------
constexpr int BATCH = 4, EDIM = 512, LDIM = 512, VDIM = 32000;
constexpr int BLROWS = BATCH * LDIM;          // 2048
constexpr int MT = 128;                       // CTA M tile
constexpr int NT = 256;                       // CTA N tile
constexpr int KC = 64;                        // K chunk (bf16) -> 128B rows
constexpr int NCHUNK = EDIM / KC;             // 8
constexpr float INV_TAU = 0.1f;

// ---------------- device scratch ----------------
__device__ __align__(256) __nv_bfloat16 g_Mb[(size_t)VDIM * EDIM];   // 32 MB
__device__ __align__(256) __nv_bfloat16 g_A[(size_t)BLROWS * EDIM];  // 2 MB
__device__ float g_up[BLROWS];
__device__ float g_down[BLROWS];

// ---------------- smem ----------------
constexpr int ASTG = MT * KC * 2;             // 16384
constexpr int BSTG = NT * KC * 2;             // 32768
constexpr int STG  = ASTG + BSTG;             // 49152 per stage
constexpr int NSTAGE = 3;
constexpr int SM_ROWACC = NSTAGE * STG;       // 147456
constexpr int SMEM_TOTAL = SM_ROWACC + MT * 4;

// ---------------- helpers ----------------
DI uint32_t smem_u32(const void* p) {
    uint32_t a;
    asm("{ .reg .u64 t; cvta.to.shared.u64 t, %1; cvt.u32.u64 %0, t; }" : "=r"(a) : "l"(p));
    return a;
}
DI uint32_t swz(uint32_t off) { return off ^ ((off >> 3) & 0x70); }  // SW128

DI void cp_async16(uint32_t dst, const void* src) {
    asm volatile("cp.async.cg.shared.global [%0], [%1], 16;" :: "r"(dst), "l"(src));
}
#define CP_COMMIT() asm volatile("cp.async.commit_group;" ::: "memory")
#define CP_WAIT1()  asm volatile("cp.async.wait_group 1;" ::: "memory")

DI void ldsm4(uint32_t* r, uint32_t addr) {
    asm volatile("ldmatrix.sync.aligned.m8n8.x4.shared.b16 {%0,%1,%2,%3}, [%4];"
                 : "=r"(r[0]), "=r"(r[1]), "=r"(r[2]), "=r"(r[3]) : "r"(addr));
}
DI void mma16816(float* c, const uint32_t* a, uint32_t b0, uint32_t b1) {
    asm volatile(
        "mma.sync.aligned.m16n8k16.row.col.f32.bf16.bf16.f32 "
        "{%0,%1,%2,%3}, {%4,%5,%6,%7}, {%8,%9}, {%0,%1,%2,%3};"
        : "+f"(c[0]), "+f"(c[1]), "+f"(c[2]), "+f"(c[3])
        : "r"(a[0]), "r"(a[1]), "r"(a[2]), "r"(a[3]), "r"(b0), "r"(b1));
}

// FFMA-only exp(INV_TAU * d): exp2 magic-number range reduction + deg-5 poly.
DI float exp_tau(float d) {
    const float S = 0.14426950408889634f;  // INV_TAU * log2(e)
    const float MAGIC = 12582912.0f;       // 1.5 * 2^23
    float yr = fmaf(d, S, MAGIC);
    int n = __float_as_int(yr);
    float t = yr - MAGIC;
    float r = fmaf(d, S, -t);
    float p = 1.3333558e-3f;
    p = fmaf(p, r, 9.6181291e-3f);
    p = fmaf(p, r, 5.5504109e-2f);
    p = fmaf(p, r, 2.4022651e-1f);
    p = fmaf(p, r, 6.9314718e-1f);
    p = fmaf(p, r, 1.0f);
    float sc = __int_as_float((n - 0x4B400000 + 127) << 23);
    return p * sc;
}

// ---------------- pre-kernels ----------------
__global__ void convertM_kernel(const float* __restrict__ M) {
    int i = blockIdx.x * blockDim.x + threadIdx.x;
    if (i < VDIM * EDIM / 2) {
        float2 v = reinterpret_cast<const float2*>(M)[i];
        reinterpret_cast<__nv_bfloat162*>(g_Mb)[i] = __floats2bfloat162_rn(v.x, v.y);
    }
}

__global__ void buildA_kernel(const float* __restrict__ DE) {
    __shared__ float tile[32][33];
    int b = blockIdx.z;
    int e0 = blockIdx.x * 32, l0 = blockIdx.y * 32;
    int tx = threadIdx.x, ty = threadIdx.y;   // (32, 8)
    const float* src = DE + (size_t)b * EDIM * LDIM;
    #pragma unroll
    for (int i = 0; i < 4; i++)
        tile[ty + i * 8][tx] = src[(size_t)(e0 + ty + i * 8) * LDIM + l0 + tx];
    __syncthreads();
    #pragma unroll
    for (int i = 0; i < 4; i++) {
        int l = l0 + ty + i * 8;
        g_A[(size_t)(b * LDIM + l) * EDIM + e0 + tx] = __float2bfloat16(tile[tx][ty + i * 8]);
    }
}

__global__ void up_kernel(const float* __restrict__ EN, const float* __restrict__ DE) {
    int bl = blockIdx.x * blockDim.x + threadIdx.x;
    if (bl >= BLROWS) return;
    int b = bl >> 9;
    int l = bl & (LDIM - 1);
    const float* en = EN + (size_t)b * EDIM * LDIM + l;
    const float* de = DE + (size_t)b * EDIM * LDIM + l;
    float s = 0.f;
    #pragma unroll 8
    for (int e = 0; e < EDIM; e++)
        s += en[(size_t)e * LDIM] * de[(size_t)e * LDIM];
    g_up[bl] = expf(INV_TAU * s);
    g_down[bl] = 0.f;
}

// ---------------- main fused GEMM + exp-reduce ----------------
DI void load_chunk(uint32_t sA, uint32_t sB, const __nv_bfloat16* Ag,
                   const __nv_bfloat16* Bg, int kc, int tid) {
    const __nv_bfloat16* as = Ag + kc * KC;
    #pragma unroll
    for (int t = 0; t < 4; t++) {
        int i = tid + t * 256;
        int r = i >> 3, j = i & 7;
        cp_async16(sA + swz(r * 128 + j * 16), as + (size_t)r * EDIM + j * 8);
    }
    const __nv_bfloat16* bs = Bg + kc * KC;
    #pragma unroll
    for (int t = 0; t < 8; t++) {
        int i = tid + t * 256;
        int r = i >> 3, j = i & 7;
        cp_async16(sB + swz(r * 128 + j * 16), bs + (size_t)r * EDIM + j * 8);
    }
}

__global__ __launch_bounds__(256, 1) void gemm_exp_kernel() {
    extern __shared__ __align__(1024) char smem[];
    const uint32_t sb = smem_u32(smem);
    const int tid = threadIdx.x;
    const int wid = tid >> 5;
    const int lid = tid & 31;
    const int warp_m = wid >> 2;     // 0..1
    const int warp_n = wid & 3;      // 0..3
    const int m0 = blockIdx.x * MT;
    const int n0 = blockIdx.y * NT;

    // zero the per-CTA row accumulator
    if (tid < MT)
        *reinterpret_cast<float*>(smem + SM_ROWACC + tid * 4) = 0.f;

    const __nv_bfloat16* Ag = g_A + (size_t)m0 * EDIM;
    const __nv_bfloat16* Bg = g_Mb + (size_t)n0 * EDIM;

    // ldmatrix addressing constants
    const int lane15 = lid & 15;
    const uint32_t koffB = (uint32_t)(lid >> 4) * 16;   // byte offset for k+8 half
    uint32_t arow[4], brow[4];
    #pragma unroll
    for (int mi = 0; mi < 4; mi++)
        arow[mi] = (uint32_t)(warp_m * 64 + mi * 16 + lane15) * 128;
    #pragma unroll
    for (int nj = 0; nj < 4; nj++)
        brow[nj] = (uint32_t)(warp_n * 64 + nj * 16 + lane15) * 128;

    float acc[4][8][4];
    #pragma unroll
    for (int mi = 0; mi < 4; mi++)
        #pragma unroll
        for (int nj = 0; nj < 8; nj++)
            #pragma unroll
            for (int q = 0; q < 4; q++)
                acc[mi][nj][q] = 0.f;

    // prologue: stages 0, 1
    load_chunk(sb, sb + ASTG, Ag, Bg, 0, tid);
    CP_COMMIT();
    load_chunk(sb + STG, sb + STG + ASTG, Ag, Bg, 1, tid);
    CP_COMMIT();

    #pragma unroll 1
    for (int c = 0; c < NCHUNK; c++) {
        CP_WAIT1();
        __syncthreads();
        if (c + 2 < NCHUNK) {
            const uint32_t s = ((c + 2) % NSTAGE) * STG;
            load_chunk(sb + s, sb + s + ASTG, Ag, Bg, c + 2, tid);
        }
        CP_COMMIT();

        const uint32_t sA = sb + (c % NSTAGE) * STG;
        const uint32_t sB = sA + ASTG;
        #pragma unroll
        for (int ks = 0; ks < 4; ks++) {
            uint32_t af[4][4], bf[4][4];
            #pragma unroll
            for (int mi = 0; mi < 4; mi++)
                ldsm4(af[mi], sA + swz(arow[mi] + ks * 32 + koffB));
            #pragma unroll
            for (int nj = 0; nj < 4; nj++)
                ldsm4(bf[nj], sB + swz(brow[nj] + ks * 32 + koffB));
            #pragma unroll
            for (int mi = 0; mi < 4; mi++)
                #pragma unroll
                for (int nj = 0; nj < 4; nj++) {
                    mma16816(acc[mi][nj * 2],     af[mi], bf[nj][0], bf[nj][2]);
                    mma16816(acc[mi][nj * 2 + 1], af[mi], bf[nj][1], bf[nj][3]);
                }
        }
    }

    // ---- epilogue: exp + row reduction ----
    __syncthreads();   // rowacc zero visible; all compute done
    float* rowacc = reinterpret_cast<float*>(smem + SM_ROWACC);
    const int groupID = lid >> 2;
    const int tig = lid & 3;
    #pragma unroll
    for (int mi = 0; mi < 4; mi++) {
        float s0 = 0.f, s1 = 0.f;
        #pragma unroll
        for (int nj = 0; nj < 8; nj++) {
            s0 += exp_tau(acc[mi][nj][0]) + exp_tau(acc[mi][nj][1]);
            s1 += exp_tau(acc[mi][nj][2]) + exp_tau(acc[mi][nj][3]);
        }
        s0 += __shfl_xor_sync(0xffffffffu, s0, 1);
        s0 += __shfl_xor_sync(0xffffffffu, s0, 2);
        s1 += __shfl_xor_sync(0xffffffffu, s1, 1);
        s1 += __shfl_xor_sync(0xffffffffu, s1, 2);
        if (tig == 0) {
            atomicAdd(&rowacc[warp_m * 64 + mi * 16 + groupID], s0);
            atomicAdd(&rowacc[warp_m * 64 + mi * 16 + groupID + 8], s1);
        }
    }
    __syncthreads();
    if (tid < MT)
        atomicAdd(&g_down[m0 + tid], rowacc[tid]);
}

// ---------------- final reduction ----------------
__global__ void finalize_kernel(float* __restrict__ out) {
    __shared__ float red[256];
    float s = 0.f;
    for (int i = threadIdx.x; i < BLROWS; i += 256)
        s += g_up[i] / g_down[i];
    red[threadIdx.x] = s;
    __syncthreads();
    #pragma unroll
    for (int st = 128; st > 0; st >>= 1) {
        if (threadIdx.x < st) red[threadIdx.x] += red[threadIdx.x + st];
        __syncthreads();
    }
    if (threadIdx.x == 0) out[0] = red[0];
}

// ---------------- launch ----------------
extern "C" void kernel_launch(void* const* d_in, const int* in_sizes, int n_in,
                              void* d_out, int out_size) {
    const float* EN = (const float*)d_in[0];
    const float* DE = (const float*)d_in[1];
    const float* M  = (const float*)d_in[2];
    float* out = (float*)d_out;

    convertM_kernel<<<(VDIM * EDIM / 2 + 255) / 256, 256>>>(M);
    buildA_kernel<<<dim3(EDIM / 32, LDIM / 32, BATCH), dim3(32, 8)>>>(DE);
    up_kernel<<<(BLROWS + 255) / 256, 256>>>(EN, DE);

    cudaFuncSetAttribute(gemm_exp_kernel,
                         cudaFuncAttributeMaxDynamicSharedMemorySize, SMEM_TOTAL);
    gemm_exp_kernel<<<dim3(BLROWS / MT, VDIM / NT), 256, SMEM_TOTAL>>>();

    finalize_kernel<<<1, 256>>>(out);
}